// round 2
// baseline (speedup 1.0000x reference)
#include <cuda_runtime.h>
#include <cuda_bf16.h>
#include <cstdint>
#include <cstddef>

#define NTOK   8192
#define HDIM   1024
#define NEXP   8
#define TOPK   2
#define IDIM   1024
#define SHI    2048
#define CAP    2560   // ceil(1.25 * 8192 * 2 / 8)

// ---------------- device scratch (static, no allocation) ----------------
__device__ int   g_topk_idx[NTOK * TOPK];
__device__ float g_topk_w[NTOK * TOPK];
__device__ int   g_etok[NEXP * CAP];
__device__ float g_ewt[NEXP * CAP];
__device__ int   g_counts[NEXP];
__device__ float g_act_r[(size_t)NEXP * CAP * IDIM];   // routed SwiGLU activations (fp32)
__device__ float g_act_s[(size_t)NTOK * SHI];          // shared SwiGLU activations (fp32)

__device__ __forceinline__ float silu_f(float x) { return x / (1.f + __expf(-x)); }

// ---------------- router: logits, softmax, top-2, normalized weights ----
__global__ void router_kernel(const float* __restrict__ x, const float* __restrict__ gw)
{
    int warp = threadIdx.x >> 5;
    int lane = threadIdx.x & 31;
    int tok  = blockIdx.x * 8 + warp;
    if (tok >= NTOK) return;
    const float* xr = x + (size_t)tok * HDIM;

    float acc[NEXP];
#pragma unroll
    for (int e = 0; e < NEXP; e++) acc[e] = 0.f;
    for (int h = lane; h < HDIM; h += 32) {
        float xv = xr[h];
#pragma unroll
        for (int e = 0; e < NEXP; e++) acc[e] += xv * gw[e * HDIM + h];
    }
#pragma unroll
    for (int e = 0; e < NEXP; e++) {
#pragma unroll
        for (int off = 16; off > 0; off >>= 1)
            acc[e] += __shfl_xor_sync(0xffffffffu, acc[e], off);
    }
    if (lane == 0) {
        float mx = acc[0];
#pragma unroll
        for (int e = 1; e < NEXP; e++) mx = fmaxf(mx, acc[e]);
        float p[NEXP]; float s = 0.f;
#pragma unroll
        for (int e = 0; e < NEXP; e++) { p[e] = expf(acc[e] - mx); s += p[e]; }
#pragma unroll
        for (int e = 0; e < NEXP; e++) p[e] /= s;
        int i0 = 0;
#pragma unroll
        for (int e = 1; e < NEXP; e++) if (p[e] > p[i0]) i0 = e;     // ties -> lower index
        int i1 = -1;
#pragma unroll
        for (int e = 0; e < NEXP; e++) {
            if (e == i0) continue;
            if (i1 < 0 || p[e] > p[i1]) i1 = e;
        }
        float w0 = p[i0], w1 = p[i1];
        float inv = 1.f / (w0 + w1 + 1e-20f);
        g_topk_idx[tok * 2 + 0] = i0;
        g_topk_idx[tok * 2 + 1] = i1;
        g_topk_w[tok * 2 + 0] = w0 * inv;
        g_topk_w[tok * 2 + 1] = w1 * inv;
    }
}

// ------------- capacity scan (exact reference flat order) + compaction ---
__global__ void scan_kernel()
{
    __shared__ int hist[256][NEXP];
    int t = threadIdx.x;
    const int per = (NTOK * TOPK) / 256;   // 64 slots per thread
    int local[NEXP];
#pragma unroll
    for (int e = 0; e < NEXP; e++) local[e] = 0;
    int base = t * per;
    for (int i = 0; i < per; i++) local[g_topk_idx[base + i]]++;
#pragma unroll
    for (int e = 0; e < NEXP; e++) hist[t][e] = local[e];
    __syncthreads();
    if (t < NEXP) {
        int run = 0;
        for (int i = 0; i < 256; i++) { int v = hist[i][t]; hist[i][t] = run; run += v; }
        g_counts[t] = run < CAP ? run : CAP;
    }
    __syncthreads();
    int off[NEXP];
#pragma unroll
    for (int e = 0; e < NEXP; e++) off[e] = hist[t][e];
    for (int i = 0; i < per; i++) {
        int slot = base + i;
        int e = g_topk_idx[slot];
        int pos = off[e]++;
        if (pos < CAP) {
            g_etok[e * CAP + pos] = slot >> 1;           // token
            g_ewt[e * CAP + pos]  = g_topk_w[slot];      // normalized weight
        }
    }
}

// ---------------- bf16-split tiled GEMMs (mma.sync m16n8k16) ------------
#define BM 64
#define BN 64
#define BK 32
#define SMP 40   // padded smem row stride (bf16 elems)

__device__ __forceinline__ void mma_bf16(float (&c)[4], const uint32_t (&a)[4],
                                         uint32_t b0, uint32_t b1)
{
    asm volatile(
        "mma.sync.aligned.m16n8k16.row.col.f32.bf16.bf16.f32 "
        "{%0,%1,%2,%3}, {%4,%5,%6,%7}, {%8,%9}, {%0,%1,%2,%3};\n"
        : "+f"(c[0]), "+f"(c[1]), "+f"(c[2]), "+f"(c[3])
        : "r"(a[0]), "r"(a[1]), "r"(a[2]), "r"(a[3]), "r"(b0), "r"(b1));
}

__device__ __forceinline__ void split_store(float4 v,
                                            __nv_bfloat16 (*dh)[SMP],
                                            __nv_bfloat16 (*dl)[SMP],
                                            int rr, int cc)
{
    float f[4] = { v.x, v.y, v.z, v.w };
    __nv_bfloat16 h[4], l[4];
#pragma unroll
    for (int j = 0; j < 4; j++) {
        h[j] = __float2bfloat16(f[j]);
        l[j] = __float2bfloat16(f[j] - __bfloat162float(h[j]));
    }
    *reinterpret_cast<__nv_bfloat162*>(&dh[rr][cc + 0]) = __halves2bfloat162(h[0], h[1]);
    *reinterpret_cast<__nv_bfloat162*>(&dh[rr][cc + 2]) = __halves2bfloat162(h[2], h[3]);
    *reinterpret_cast<__nv_bfloat162*>(&dl[rr][cc + 0]) = __halves2bfloat162(l[0], l[1]);
    *reinterpret_cast<__nv_bfloat162*>(&dl[rr][cc + 2]) = __halves2bfloat162(l[2], l[3]);
}

// GLU GEMM: act[m, n] = silu(A@Bg^T) * (A@Bu^T); optional row gather via rowidx.
__global__ __launch_bounds__(256) void gemm_glu_kernel(
    const float* __restrict__ A, int lda,
    const int* __restrict__ rowidx, int tokstride,
    const float* __restrict__ Bg_, const float* __restrict__ Bu_, size_t bstride,
    float* __restrict__ actout, size_t actstride, int ldo,
    int Kdim)
{
    __shared__ __align__(16) __nv_bfloat16 As[2][BM][SMP];
    __shared__ __align__(16) __nv_bfloat16 Bgs[2][BN][SMP];
    __shared__ __align__(16) __nv_bfloat16 Bus[2][BN][SMP];

    int e = blockIdx.z;
    const float* Bg = Bg_ + (size_t)e * bstride;
    const float* Bu = Bu_ + (size_t)e * bstride;
    float* aout = actout + (size_t)e * actstride;
    const int* ridx = rowidx ? rowidx + (size_t)e * tokstride : nullptr;

    int m0 = blockIdx.y * BM, n0 = blockIdx.x * BN;
    int tid = threadIdx.x;
    int lane = tid & 31, warp = tid >> 5;
    int wm = warp & 3, wn = warp >> 2;
    int g = lane >> 2, t4 = lane & 3;

    int lrow[2], lcol[2];
    size_t arowg[2];
#pragma unroll
    for (int r = 0; r < 2; r++) {
        int idx = tid + 256 * r;
        lrow[r] = idx >> 3;
        lcol[r] = (idx & 7) * 4;
        int gm = m0 + lrow[r];
        int tokr = ridx ? ridx[gm] : gm;
        arowg[r] = (size_t)tokr * lda;
    }

    float accG[4][4], accU[4][4];
#pragma unroll
    for (int j = 0; j < 4; j++)
#pragma unroll
        for (int i = 0; i < 4; i++) { accG[j][i] = 0.f; accU[j][i] = 0.f; }

    for (int k0 = 0; k0 < Kdim; k0 += BK) {
#pragma unroll
        for (int r = 0; r < 2; r++) {
            float4 av = *(const float4*)(A  + arowg[r] + k0 + lcol[r]);
            float4 gv = *(const float4*)(Bg + (size_t)(n0 + lrow[r]) * Kdim + k0 + lcol[r]);
            float4 uv = *(const float4*)(Bu + (size_t)(n0 + lrow[r]) * Kdim + k0 + lcol[r]);
            split_store(av, As[0],  As[1],  lrow[r], lcol[r]);
            split_store(gv, Bgs[0], Bgs[1], lrow[r], lcol[r]);
            split_store(uv, Bus[0], Bus[1], lrow[r], lcol[r]);
        }
        __syncthreads();
#pragma unroll
        for (int kk = 0; kk < 2; kk++) {
            int kb = kk * 16 + 2 * t4;
            int ra = wm * 16 + g;
            uint32_t ah[4], al[4];
            ah[0] = *(const uint32_t*)&As[0][ra][kb];
            ah[1] = *(const uint32_t*)&As[0][ra + 8][kb];
            ah[2] = *(const uint32_t*)&As[0][ra][kb + 8];
            ah[3] = *(const uint32_t*)&As[0][ra + 8][kb + 8];
            al[0] = *(const uint32_t*)&As[1][ra][kb];
            al[1] = *(const uint32_t*)&As[1][ra + 8][kb];
            al[2] = *(const uint32_t*)&As[1][ra][kb + 8];
            al[3] = *(const uint32_t*)&As[1][ra + 8][kb + 8];
#pragma unroll
            for (int j = 0; j < 4; j++) {
                int nb = wn * 32 + j * 8 + g;
                uint32_t gh0 = *(const uint32_t*)&Bgs[0][nb][kb];
                uint32_t gh1 = *(const uint32_t*)&Bgs[0][nb][kb + 8];
                uint32_t gl0 = *(const uint32_t*)&Bgs[1][nb][kb];
                uint32_t gl1 = *(const uint32_t*)&Bgs[1][nb][kb + 8];
                mma_bf16(accG[j], ah, gh0, gh1);
                mma_bf16(accG[j], ah, gl0, gl1);
                mma_bf16(accG[j], al, gh0, gh1);
                uint32_t uh0 = *(const uint32_t*)&Bus[0][nb][kb];
                uint32_t uh1 = *(const uint32_t*)&Bus[0][nb][kb + 8];
                uint32_t ul0 = *(const uint32_t*)&Bus[1][nb][kb];
                uint32_t ul1 = *(const uint32_t*)&Bus[1][nb][kb + 8];
                mma_bf16(accU[j], ah, uh0, uh1);
                mma_bf16(accU[j], ah, ul0, ul1);
                mma_bf16(accU[j], al, uh0, uh1);
            }
        }
        __syncthreads();
    }

#pragma unroll
    for (int j = 0; j < 4; j++) {
        int colg = n0 + wn * 32 + j * 8 + 2 * t4;
        int r0 = m0 + wm * 16 + g;
        int r1 = r0 + 8;
        aout[(size_t)r0 * ldo + colg]     = silu_f(accG[j][0]) * accU[j][0];
        aout[(size_t)r0 * ldo + colg + 1] = silu_f(accG[j][1]) * accU[j][1];
        aout[(size_t)r1 * ldo + colg]     = silu_f(accG[j][2]) * accU[j][2];
        aout[(size_t)r1 * ldo + colg + 1] = silu_f(accG[j][3]) * accU[j][3];
    }
}

// Down GEMM: out[tok, n] (+)= w * (A @ B^T); scatter via rowidx/wts; counts masks padded rows.
__global__ __launch_bounds__(256) void gemm_down_kernel(
    const float* __restrict__ A_, int lda, size_t astride,
    const float* __restrict__ B_, size_t bstride,
    const int* __restrict__ rowidx, const float* __restrict__ wts, int tokstride,
    const int* __restrict__ counts, int Mtotal,
    float* __restrict__ out, int ldo, int Kdim, int accumulate)
{
    __shared__ __align__(16) __nv_bfloat16 As[2][BM][SMP];
    __shared__ __align__(16) __nv_bfloat16 Bs[2][BN][SMP];

    int e = blockIdx.z;
    const float* A = A_ + (size_t)e * astride;
    const float* B = B_ + (size_t)e * bstride;

    int m0 = blockIdx.y * BM, n0 = blockIdx.x * BN;
    int tid = threadIdx.x;
    int lane = tid & 31, warp = tid >> 5;
    int wm = warp & 3, wn = warp >> 2;
    int g = lane >> 2, t4 = lane & 3;

    int lrow[2], lcol[2];
#pragma unroll
    for (int r = 0; r < 2; r++) {
        int idx = tid + 256 * r;
        lrow[r] = idx >> 3;
        lcol[r] = (idx & 7) * 4;
    }

    float acc[4][4];
#pragma unroll
    for (int j = 0; j < 4; j++)
#pragma unroll
        for (int i = 0; i < 4; i++) acc[j][i] = 0.f;

    for (int k0 = 0; k0 < Kdim; k0 += BK) {
#pragma unroll
        for (int r = 0; r < 2; r++) {
            float4 av = *(const float4*)(A + (size_t)(m0 + lrow[r]) * lda + k0 + lcol[r]);
            float4 bv = *(const float4*)(B + (size_t)(n0 + lrow[r]) * Kdim + k0 + lcol[r]);
            split_store(av, As[0], As[1], lrow[r], lcol[r]);
            split_store(bv, Bs[0], Bs[1], lrow[r], lcol[r]);
        }
        __syncthreads();
#pragma unroll
        for (int kk = 0; kk < 2; kk++) {
            int kb = kk * 16 + 2 * t4;
            int ra = wm * 16 + g;
            uint32_t ah[4], al[4];
            ah[0] = *(const uint32_t*)&As[0][ra][kb];
            ah[1] = *(const uint32_t*)&As[0][ra + 8][kb];
            ah[2] = *(const uint32_t*)&As[0][ra][kb + 8];
            ah[3] = *(const uint32_t*)&As[0][ra + 8][kb + 8];
            al[0] = *(const uint32_t*)&As[1][ra][kb];
            al[1] = *(const uint32_t*)&As[1][ra + 8][kb];
            al[2] = *(const uint32_t*)&As[1][ra][kb + 8];
            al[3] = *(const uint32_t*)&As[1][ra + 8][kb + 8];
#pragma unroll
            for (int j = 0; j < 4; j++) {
                int nb = wn * 32 + j * 8 + g;
                uint32_t bh0 = *(const uint32_t*)&Bs[0][nb][kb];
                uint32_t bh1 = *(const uint32_t*)&Bs[0][nb][kb + 8];
                uint32_t bl0 = *(const uint32_t*)&Bs[1][nb][kb];
                uint32_t bl1 = *(const uint32_t*)&Bs[1][nb][kb + 8];
                mma_bf16(acc[j], ah, bh0, bh1);
                mma_bf16(acc[j], ah, bl0, bl1);
                mma_bf16(acc[j], al, bh0, bh1);
            }
        }
        __syncthreads();
    }

    int Mv = counts ? counts[e] : Mtotal;
#pragma unroll
    for (int j = 0; j < 4; j++) {
        int colg = n0 + wn * 32 + j * 8 + 2 * t4;
        int r0 = m0 + wm * 16 + g;
#pragma unroll
        for (int half = 0; half < 2; half++) {
            int r = r0 + half * 8;
            if (r < Mv) {
                int tok; float w;
                if (rowidx) { tok = rowidx[(size_t)e * tokstride + r]; w = wts[(size_t)e * tokstride + r]; }
                else        { tok = r; w = 1.f; }
                float v0 = acc[j][half * 2 + 0] * w;
                float v1 = acc[j][half * 2 + 1] * w;
                if (accumulate) {
                    atomicAdd(&out[(size_t)tok * ldo + colg],     v0);
                    atomicAdd(&out[(size_t)tok * ldo + colg + 1], v1);
                } else {
                    out[(size_t)tok * ldo + colg]     = v0;
                    out[(size_t)tok * ldo + colg + 1] = v1;
                }
            }
        }
    }
}

// ---------------- launch ----------------
extern "C" void kernel_launch(void* const* d_in, const int* in_sizes, int n_in,
                              void* d_out, int out_size)
{
    const float* x       = (const float*)d_in[0];
    const float* gate_w  = (const float*)d_in[1];
    const float* we_gate = (const float*)d_in[2];
    const float* we_up   = (const float*)d_in[3];
    const float* we_down = (const float*)d_in[4];
    const float* ws_gate = (const float*)d_in[5];
    const float* ws_up   = (const float*)d_in[6];
    const float* ws_down = (const float*)d_in[7];
    float* out = (float*)d_out;

    float *act_r, *act_s, *ewt;
    int *etok, *counts;
    cudaGetSymbolAddress((void**)&act_r,  g_act_r);
    cudaGetSymbolAddress((void**)&act_s,  g_act_s);
    cudaGetSymbolAddress((void**)&etok,   g_etok);
    cudaGetSymbolAddress((void**)&ewt,    g_ewt);
    cudaGetSymbolAddress((void**)&counts, g_counts);

    dim3 blk(256);

    router_kernel<<<NTOK / 8, 256>>>(x, gate_w);
    scan_kernel<<<1, 256>>>();

    // routed gate/up + SwiGLU  -> g_act_r
    gemm_glu_kernel<<<dim3(IDIM / BN, CAP / BM, NEXP), blk>>>(
        x, HDIM, etok, CAP, we_gate, we_up, (size_t)IDIM * HDIM,
        act_r, (size_t)CAP * IDIM, IDIM, HDIM);

    // shared gate/up + SwiGLU -> g_act_s
    gemm_glu_kernel<<<dim3(SHI / BN, NTOK / BM, 1), blk>>>(
        x, HDIM, nullptr, 0, ws_gate, ws_up, 0,
        act_s, 0, SHI, HDIM);

    // shared down-proj: writes out (initializes the poisoned buffer)
    gemm_down_kernel<<<dim3(HDIM / BN, NTOK / BM, 1), blk>>>(
        act_s, SHI, 0, ws_down, 0,
        nullptr, nullptr, 0, nullptr, NTOK,
        out, HDIM, SHI, /*accumulate=*/0);

    // routed down-proj: weighted scatter atomicAdd into out
    gemm_down_kernel<<<dim3(HDIM / BN, CAP / BM, NEXP), blk>>>(
        act_r, IDIM, (size_t)CAP * IDIM, we_down, (size_t)HDIM * IDIM,
        etok, ewt, CAP, counts, 0,
        out, HDIM, IDIM, /*accumulate=*/1);
}

// round 4
// speedup vs baseline: 1.2062x; 1.2062x over previous
#include <cuda_runtime.h>
#include <cuda_bf16.h>
#include <cstdint>
#include <cstddef>

#define NTOK 8192
#define HDIM 1024
#define NEXP 8
#define TOPK 2
#define IDIM 1024
#define SHI  2048
#define CAP  2560   // ceil(1.25 * 8192 * 2 / 8)

typedef __nv_bfloat16 bf16;

// ---------------- device scratch ----------------
__device__ int   g_topk_idx[NTOK * TOPK];
__device__ float g_topk_w[NTOK * TOPK];
__device__ int   g_etok[NEXP * CAP];
__device__ float g_ewt[NEXP * CAP];
__device__ int   g_counts[NEXP];

__device__ __align__(128) bf16 g_x_h[NTOK * HDIM], g_x_l[NTOK * HDIM];
__device__ __align__(128) bf16 g_wg_h[NEXP * IDIM * HDIM], g_wg_l[NEXP * IDIM * HDIM];
__device__ __align__(128) bf16 g_wu_h[NEXP * IDIM * HDIM], g_wu_l[NEXP * IDIM * HDIM];
__device__ __align__(128) bf16 g_wd_h[NEXP * HDIM * IDIM], g_wd_l[NEXP * HDIM * IDIM];
__device__ __align__(128) bf16 g_sg_h[SHI * HDIM], g_sg_l[SHI * HDIM];
__device__ __align__(128) bf16 g_su_h[SHI * HDIM], g_su_l[SHI * HDIM];
__device__ __align__(128) bf16 g_sd_h[HDIM * SHI], g_sd_l[HDIM * SHI];
__device__ __align__(128) bf16 g_ar_h[(size_t)NEXP * CAP * IDIM], g_ar_l[(size_t)NEXP * CAP * IDIM];
__device__ __align__(128) bf16 g_as_h[(size_t)NTOK * SHI], g_as_l[(size_t)NTOK * SHI];

__device__ __forceinline__ float silu_f(float x) { return x / (1.f + __expf(-x)); }
__device__ __forceinline__ uint32_t sw64(uint32_t b) { return b ^ ((b >> 3) & 0x30); }

__device__ __forceinline__ void cp16(uint32_t dst, const void* src) {
    asm volatile("cp.async.cg.shared.global [%0], [%1], 16;" :: "r"(dst), "l"(src));
}
#define CP_COMMIT() asm volatile("cp.async.commit_group;")
#define CP_WAIT2()  asm volatile("cp.async.wait_group 2;")

__device__ __forceinline__ void ldsm4(uint32_t* r, uint32_t addr) {
    asm volatile("ldmatrix.sync.aligned.m8n8.x4.shared.b16 {%0,%1,%2,%3}, [%4];"
                 : "=r"(r[0]), "=r"(r[1]), "=r"(r[2]), "=r"(r[3]) : "r"(addr));
}

__device__ __forceinline__ void mma_bf16(float (&c)[4], const uint32_t (&a)[4],
                                         uint32_t b0, uint32_t b1)
{
    asm volatile(
        "mma.sync.aligned.m16n8k16.row.col.f32.bf16.bf16.f32 "
        "{%0,%1,%2,%3}, {%4,%5,%6,%7}, {%8,%9}, {%0,%1,%2,%3};\n"
        : "+f"(c[0]), "+f"(c[1]), "+f"(c[2]), "+f"(c[3])
        : "r"(a[0]), "r"(a[1]), "r"(a[2]), "r"(a[3]), "r"(b0), "r"(b1));
}

__device__ __forceinline__ void store_pair(bf16* hi, bf16* lo, size_t off, float v0, float v1) {
    bf16 h0 = __float2bfloat16(v0), h1 = __float2bfloat16(v1);
    bf16 l0 = __float2bfloat16(v0 - __bfloat162float(h0));
    bf16 l1 = __float2bfloat16(v1 - __bfloat162float(h1));
    *reinterpret_cast<__nv_bfloat162*>(hi + off) = __halves2bfloat162(h0, h1);
    *reinterpret_cast<__nv_bfloat162*>(lo + off) = __halves2bfloat162(l0, l1);
}

// ---------------- fp32 -> bf16 hi/lo conversion ----------------
__global__ void convert_kernel(const float* __restrict__ s, bf16* __restrict__ hi,
                               bf16* __restrict__ lo, int n)
{
    int i = (blockIdx.x * 256 + threadIdx.x) * 4;
    if (i >= n) return;
    float4 v = *(const float4*)(s + i);
    store_pair(hi, lo, i,     v.x, v.y);
    store_pair(hi, lo, i + 2, v.z, v.w);
}

// ---------------- router ----------------
__global__ void router_kernel(const float* __restrict__ x, const float* __restrict__ gw)
{
    int warp = threadIdx.x >> 5;
    int lane = threadIdx.x & 31;
    int tok  = blockIdx.x * 8 + warp;
    if (tok >= NTOK) return;
    const float* xr = x + (size_t)tok * HDIM;

    float acc[NEXP];
#pragma unroll
    for (int e = 0; e < NEXP; e++) acc[e] = 0.f;
    for (int h = lane; h < HDIM; h += 32) {
        float xv = xr[h];
#pragma unroll
        for (int e = 0; e < NEXP; e++) acc[e] += xv * gw[e * HDIM + h];
    }
#pragma unroll
    for (int e = 0; e < NEXP; e++) {
#pragma unroll
        for (int off = 16; off > 0; off >>= 1)
            acc[e] += __shfl_xor_sync(0xffffffffu, acc[e], off);
    }
    if (lane == 0) {
        float mx = acc[0];
#pragma unroll
        for (int e = 1; e < NEXP; e++) mx = fmaxf(mx, acc[e]);
        float p[NEXP]; float s = 0.f;
#pragma unroll
        for (int e = 0; e < NEXP; e++) { p[e] = expf(acc[e] - mx); s += p[e]; }
#pragma unroll
        for (int e = 0; e < NEXP; e++) p[e] /= s;
        int i0 = 0;
#pragma unroll
        for (int e = 1; e < NEXP; e++) if (p[e] > p[i0]) i0 = e;
        int i1 = -1;
#pragma unroll
        for (int e = 0; e < NEXP; e++) {
            if (e == i0) continue;
            if (i1 < 0 || p[e] > p[i1]) i1 = e;
        }
        float w0 = p[i0], w1 = p[i1];
        float inv = 1.f / (w0 + w1 + 1e-20f);
        g_topk_idx[tok * 2 + 0] = i0;
        g_topk_idx[tok * 2 + 1] = i1;
        g_topk_w[tok * 2 + 0] = w0 * inv;
        g_topk_w[tok * 2 + 1] = w1 * inv;
    }
}

// ---------------- capacity scan + compaction (reference order) ----------------
__global__ void scan_kernel()
{
    __shared__ int hist[256][NEXP];
    int t = threadIdx.x;
    const int per = (NTOK * TOPK) / 256;
    int local[NEXP];
#pragma unroll
    for (int e = 0; e < NEXP; e++) local[e] = 0;
    int base = t * per;
    for (int i = 0; i < per; i++) local[g_topk_idx[base + i]]++;
#pragma unroll
    for (int e = 0; e < NEXP; e++) hist[t][e] = local[e];
    __syncthreads();
    if (t < NEXP) {
        int run = 0;
        for (int i = 0; i < 256; i++) { int v = hist[i][t]; hist[i][t] = run; run += v; }
        g_counts[t] = run < CAP ? run : CAP;
    }
    __syncthreads();
    int off[NEXP];
#pragma unroll
    for (int e = 0; e < NEXP; e++) off[e] = hist[t][e];
    for (int i = 0; i < per; i++) {
        int slot = base + i;
        int e = g_topk_idx[slot];
        int pos = off[e]++;
        if (pos < CAP) {
            g_etok[e * CAP + pos] = slot >> 1;
            g_ewt[e * CAP + pos]  = g_topk_w[slot];
        }
    }
}

// ============================================================================
// GLU GEMM: O = silu(A@G^T) * (A@U^T) -> bf16 hi/lo. 128x64 tiles, BK=32,
// 3-stage cp.async, ldmatrix, bf16 hi/lo 3-product mma.
// ============================================================================
__global__ __launch_bounds__(256, 1) void glu_bf16_kernel(
    const bf16* __restrict__ Ahi, const bf16* __restrict__ Alo, int lda,
    const int* __restrict__ rowidx,
    const bf16* __restrict__ Ghi_, const bf16* __restrict__ Glo_,
    const bf16* __restrict__ Uhi_, const bf16* __restrict__ Ulo_, size_t bstride,
    bf16* __restrict__ Ohi_, bf16* __restrict__ Olo_, size_t ostride, int ldo,
    int Kdim, const int* __restrict__ counts)
{
    extern __shared__ __align__(128) char smdyn[];
    const int e = blockIdx.z;
    const int m0 = blockIdx.y * 128, n0 = blockIdx.x * 64;
    if (counts && m0 >= counts[e]) return;

    const char* Gh = (const char*)(Ghi_ + (size_t)e * bstride);
    const char* Gl = (const char*)(Glo_ + (size_t)e * bstride);
    const char* Uh = (const char*)(Uhi_ + (size_t)e * bstride);
    const char* Ul = (const char*)(Ulo_ + (size_t)e * bstride);
    bf16* Oh = Ohi_ + (size_t)e * ostride;
    bf16* Ol = Olo_ + (size_t)e * ostride;
    const int* ridx = rowidx ? rowidx + e * CAP : nullptr;

    const int tid = threadIdx.x;
    uint32_t smb = (uint32_t)__cvta_generic_to_shared(smdyn);
    const int ST = 32768;
    const int AH = 0, AL = 8192, GHo = 16384, GLo = 20480, UHo = 24576, ULo = 28672;

    // ---- load assignments ----
    int ar0 = tid >> 2, ac = tid & 3;          // A rows 0..63, 16B chunk 0..3
    int ar1 = ar0 + 64;
    int tok0 = ridx ? ridx[m0 + ar0] : m0 + ar0;
    int tok1 = ridx ? ridx[m0 + ar1] : m0 + ar1;
    size_t ab0 = ((size_t)tok0 * lda + ac * 8) * 2;
    size_t ab1 = ((size_t)tok1 * lda + ac * 8) * 2;
    size_t bb  = ((size_t)(n0 + ar0) * Kdim + ac * 8) * 2;
    uint32_t dA0 = sw64(ar0 * 64 + ac * 16);
    uint32_t dA1 = sw64(ar1 * 64 + ac * 16);
    const char* pAh = (const char*)Ahi;
    const char* pAl = (const char*)Alo;

    auto load_stage = [&](int kt, int buf) {
        uint32_t s = smb + buf * ST;
        long kb = (long)kt * 64;          // 32 elems * 2B
        cp16(s + AH + dA0, pAh + ab0 + kb);
        cp16(s + AH + dA1, pAh + ab1 + kb);
        cp16(s + AL + dA0, pAl + ab0 + kb);
        cp16(s + AL + dA1, pAl + ab1 + kb);
        cp16(s + GHo + dA0, Gh + bb + kb);
        cp16(s + GLo + dA0, Gl + bb + kb);
        cp16(s + UHo + dA0, Uh + bb + kb);
        cp16(s + ULo + dA0, Ul + bb + kb);
    };

    // ---- compute setup ----
    const int lane = tid & 31, warp = tid >> 5;
    const int wm = warp & 3, wn = warp >> 2;
    const int lr = lane & 15, lc = (lane >> 4) * 16;

    float accG[2][4][4], accU[2][4][4];
#pragma unroll
    for (int mt = 0; mt < 2; mt++)
#pragma unroll
        for (int nf = 0; nf < 4; nf++)
#pragma unroll
            for (int i = 0; i < 4; i++) { accG[mt][nf][i] = 0.f; accU[mt][nf][i] = 0.f; }

    auto comp_stage = [&](int buf) {
        uint32_t s = smb + buf * ST;
#pragma unroll
        for (int kk = 0; kk < 2; kk++) {
            uint32_t ah[2][4], al[2][4];
#pragma unroll
            for (int mt = 0; mt < 2; mt++) {
                uint32_t o = sw64((wm * 32 + mt * 16 + lr) * 64 + kk * 32 + lc);
                ldsm4(ah[mt], s + AH + o);
                ldsm4(al[mt], s + AL + o);
            }
            uint32_t bgh[2][4], bgl[2][4], buh[2][4], bul[2][4];
#pragma unroll
            for (int nt = 0; nt < 2; nt++) {
                uint32_t o = sw64((wn * 32 + nt * 16 + lr) * 64 + kk * 32 + lc);
                ldsm4(bgh[nt], s + GHo + o);
                ldsm4(bgl[nt], s + GLo + o);
                ldsm4(buh[nt], s + UHo + o);
                ldsm4(bul[nt], s + ULo + o);
            }
#pragma unroll
            for (int mt = 0; mt < 2; mt++) {
#pragma unroll
                for (int nf = 0; nf < 4; nf++) {
                    int nt = nf >> 1, sb = nf & 1;
                    mma_bf16(accG[mt][nf], ah[mt], bgh[nt][sb], bgh[nt][sb + 2]);
                    mma_bf16(accG[mt][nf], ah[mt], bgl[nt][sb], bgl[nt][sb + 2]);
                    mma_bf16(accG[mt][nf], al[mt], bgh[nt][sb], bgh[nt][sb + 2]);
                    mma_bf16(accU[mt][nf], ah[mt], buh[nt][sb], buh[nt][sb + 2]);
                    mma_bf16(accU[mt][nf], ah[mt], bul[nt][sb], bul[nt][sb + 2]);
                    mma_bf16(accU[mt][nf], al[mt], buh[nt][sb], buh[nt][sb + 2]);
                }
            }
        }
    };

    // ---- pipeline ----
    const int KT = Kdim >> 5;
    load_stage(0, 0); CP_COMMIT();
    load_stage(1, 1); CP_COMMIT();
    for (int kt = 0; kt < KT; kt++) {
        int nk = kt + 2;
        if (nk < KT) load_stage(nk, nk % 3);
        CP_COMMIT();
        CP_WAIT2();
        __syncthreads();
        comp_stage(kt % 3);
        __syncthreads();
    }

    // ---- epilogue: silu(g)*u -> bf16 hi/lo ----
    int r0e = m0 + wm * 32 + (lane >> 2);
    int c0e = n0 + wn * 32 + (lane & 3) * 2;
#pragma unroll
    for (int mt = 0; mt < 2; mt++) {
#pragma unroll
        for (int nf = 0; nf < 4; nf++) {
            int r = r0e + mt * 16;
            int c = c0e + nf * 8;
            float v0 = silu_f(accG[mt][nf][0]) * accU[mt][nf][0];
            float v1 = silu_f(accG[mt][nf][1]) * accU[mt][nf][1];
            float v2 = silu_f(accG[mt][nf][2]) * accU[mt][nf][2];
            float v3 = silu_f(accG[mt][nf][3]) * accU[mt][nf][3];
            store_pair(Oh, Ol, (size_t)r * ldo + c, v0, v1);
            store_pair(Oh, Ol, (size_t)(r + 8) * ldo + c, v2, v3);
        }
    }
}

// ============================================================================
// Down GEMM: out[tok,n] (+)= w * (A@B^T), fp32 out (store or atomicAdd)
// ============================================================================
__global__ __launch_bounds__(256, 1) void down_bf16_kernel(
    const bf16* __restrict__ Ahi_, const bf16* __restrict__ Alo_, int lda, size_t astride,
    const bf16* __restrict__ Bhi_, const bf16* __restrict__ Blo_, size_t bstride,
    const int* __restrict__ rowidx, const float* __restrict__ wts,
    const int* __restrict__ counts, int Mtotal,
    float* __restrict__ out, int ldo, int Kdim, int accumulate)
{
    extern __shared__ __align__(128) char smdyn[];
    const int e = blockIdx.z;
    const int m0 = blockIdx.y * 128, n0 = blockIdx.x * 64;
    if (counts && m0 >= counts[e]) return;

    const char* pAh = (const char*)(Ahi_ + (size_t)e * astride);
    const char* pAl = (const char*)(Alo_ + (size_t)e * astride);
    const char* pBh = (const char*)(Bhi_ + (size_t)e * bstride);
    const char* pBl = (const char*)(Blo_ + (size_t)e * bstride);

    const int tid = threadIdx.x;
    uint32_t smb = (uint32_t)__cvta_generic_to_shared(smdyn);
    const int ST = 24576;
    const int AH = 0, AL = 8192, BH = 16384, BL = 20480;

    int ar0 = tid >> 2, ac = tid & 3;
    int ar1 = ar0 + 64;
    size_t ab0 = ((size_t)(m0 + ar0) * lda + ac * 8) * 2;
    size_t ab1 = ((size_t)(m0 + ar1) * lda + ac * 8) * 2;
    size_t bb  = ((size_t)(n0 + ar0) * Kdim + ac * 8) * 2;
    uint32_t dA0 = sw64(ar0 * 64 + ac * 16);
    uint32_t dA1 = sw64(ar1 * 64 + ac * 16);

    auto load_stage = [&](int kt, int buf) {
        uint32_t s = smb + buf * ST;
        long kb = (long)kt * 64;
        cp16(s + AH + dA0, pAh + ab0 + kb);
        cp16(s + AH + dA1, pAh + ab1 + kb);
        cp16(s + AL + dA0, pAl + ab0 + kb);
        cp16(s + AL + dA1, pAl + ab1 + kb);
        cp16(s + BH + dA0, pBh + bb + kb);
        cp16(s + BL + dA0, pBl + bb + kb);
    };

    const int lane = tid & 31, warp = tid >> 5;
    const int wm = warp & 3, wn = warp >> 2;
    const int lr = lane & 15, lc = (lane >> 4) * 16;

    float acc[2][4][4];
#pragma unroll
    for (int mt = 0; mt < 2; mt++)
#pragma unroll
        for (int nf = 0; nf < 4; nf++)
#pragma unroll
            for (int i = 0; i < 4; i++) acc[mt][nf][i] = 0.f;

    auto comp_stage = [&](int buf) {
        uint32_t s = smb + buf * ST;
#pragma unroll
        for (int kk = 0; kk < 2; kk++) {
            uint32_t ah[2][4], al[2][4];
#pragma unroll
            for (int mt = 0; mt < 2; mt++) {
                uint32_t o = sw64((wm * 32 + mt * 16 + lr) * 64 + kk * 32 + lc);
                ldsm4(ah[mt], s + AH + o);
                ldsm4(al[mt], s + AL + o);
            }
            uint32_t bh[2][4], bl[2][4];
#pragma unroll
            for (int nt = 0; nt < 2; nt++) {
                uint32_t o = sw64((wn * 32 + nt * 16 + lr) * 64 + kk * 32 + lc);
                ldsm4(bh[nt], s + BH + o);
                ldsm4(bl[nt], s + BL + o);
            }
#pragma unroll
            for (int mt = 0; mt < 2; mt++) {
#pragma unroll
                for (int nf = 0; nf < 4; nf++) {
                    int nt = nf >> 1, sb = nf & 1;
                    mma_bf16(acc[mt][nf], ah[mt], bh[nt][sb], bh[nt][sb + 2]);
                    mma_bf16(acc[mt][nf], ah[mt], bl[nt][sb], bl[nt][sb + 2]);
                    mma_bf16(acc[mt][nf], al[mt], bh[nt][sb], bh[nt][sb + 2]);
                }
            }
        }
    };

    const int KT = Kdim >> 5;
    load_stage(0, 0); CP_COMMIT();
    load_stage(1, 1); CP_COMMIT();
    for (int kt = 0; kt < KT; kt++) {
        int nk = kt + 2;
        if (nk < KT) load_stage(nk, nk % 3);
        CP_COMMIT();
        CP_WAIT2();
        __syncthreads();
        comp_stage(kt % 3);
        __syncthreads();
    }

    int Mv = counts ? counts[e] : Mtotal;
    int r0e = m0 + wm * 32 + (lane >> 2);
    int c0e = n0 + wn * 32 + (lane & 3) * 2;
#pragma unroll
    for (int mt = 0; mt < 2; mt++) {
#pragma unroll
        for (int nf = 0; nf < 4; nf++) {
            int c = c0e + nf * 8;
#pragma unroll
            for (int half = 0; half < 2; half++) {
                int r = r0e + mt * 16 + half * 8;
                if (r < Mv) {
                    int tok; float w;
                    if (rowidx) { tok = rowidx[e * CAP + r]; w = wts[e * CAP + r]; }
                    else        { tok = r; w = 1.f; }
                    float v0 = acc[mt][nf][half * 2 + 0] * w;
                    float v1 = acc[mt][nf][half * 2 + 1] * w;
                    if (accumulate) {
                        atomicAdd(&out[(size_t)tok * ldo + c],     v0);
                        atomicAdd(&out[(size_t)tok * ldo + c + 1], v1);
                    } else {
                        out[(size_t)tok * ldo + c]     = v0;
                        out[(size_t)tok * ldo + c + 1] = v1;
                    }
                }
            }
        }
    }
}

// ---------------- launch ----------------
extern "C" void kernel_launch(void* const* d_in, const int* in_sizes, int n_in,
                              void* d_out, int out_size)
{
    const float* x       = (const float*)d_in[0];
    const float* gate_w  = (const float*)d_in[1];
    const float* we_gate = (const float*)d_in[2];
    const float* we_up   = (const float*)d_in[3];
    const float* we_down = (const float*)d_in[4];
    const float* ws_gate = (const float*)d_in[5];
    const float* ws_up   = (const float*)d_in[6];
    const float* ws_down = (const float*)d_in[7];
    float* out = (float*)d_out;

    static bool attr_done = false;
    // (idempotent; safe to call every time — not a stream op)
    cudaFuncSetAttribute(glu_bf16_kernel,  cudaFuncAttributeMaxDynamicSharedMemorySize, 3 * 32768);
    cudaFuncSetAttribute(down_bf16_kernel, cudaFuncAttributeMaxDynamicSharedMemorySize, 3 * 24576);
    (void)attr_done;

    bf16 *x_h, *x_l, *wg_h, *wg_l, *wu_h, *wu_l, *wd_h, *wd_l;
    bf16 *sg_h, *sg_l, *su_h, *su_l, *sd_h, *sd_l;
    bf16 *ar_h, *ar_l, *as_h, *as_l;
    int *etok, *counts; float *ewt;
    cudaGetSymbolAddress((void**)&x_h, g_x_h);   cudaGetSymbolAddress((void**)&x_l, g_x_l);
    cudaGetSymbolAddress((void**)&wg_h, g_wg_h); cudaGetSymbolAddress((void**)&wg_l, g_wg_l);
    cudaGetSymbolAddress((void**)&wu_h, g_wu_h); cudaGetSymbolAddress((void**)&wu_l, g_wu_l);
    cudaGetSymbolAddress((void**)&wd_h, g_wd_h); cudaGetSymbolAddress((void**)&wd_l, g_wd_l);
    cudaGetSymbolAddress((void**)&sg_h, g_sg_h); cudaGetSymbolAddress((void**)&sg_l, g_sg_l);
    cudaGetSymbolAddress((void**)&su_h, g_su_h); cudaGetSymbolAddress((void**)&su_l, g_su_l);
    cudaGetSymbolAddress((void**)&sd_h, g_sd_h); cudaGetSymbolAddress((void**)&sd_l, g_sd_l);
    cudaGetSymbolAddress((void**)&ar_h, g_ar_h); cudaGetSymbolAddress((void**)&ar_l, g_ar_l);
    cudaGetSymbolAddress((void**)&as_h, g_as_h); cudaGetSymbolAddress((void**)&as_l, g_as_l);
    cudaGetSymbolAddress((void**)&etok, g_etok);
    cudaGetSymbolAddress((void**)&ewt,  g_ewt);
    cudaGetSymbolAddress((void**)&counts, g_counts);

    auto cvt = [&](const float* s, bf16* h, bf16* l, size_t n) {
        int blocks = (int)((n / 4 + 255) / 256);
        convert_kernel<<<blocks, 256>>>(s, h, l, (int)n);
    };

    // conversions
    cvt(x,       x_h,  x_l,  (size_t)NTOK * HDIM);
    cvt(we_gate, wg_h, wg_l, (size_t)NEXP * IDIM * HDIM);
    cvt(we_up,   wu_h, wu_l, (size_t)NEXP * IDIM * HDIM);
    cvt(we_down, wd_h, wd_l, (size_t)NEXP * HDIM * IDIM);
    cvt(ws_gate, sg_h, sg_l, (size_t)SHI * HDIM);
    cvt(ws_up,   su_h, su_l, (size_t)SHI * HDIM);
    cvt(ws_down, sd_h, sd_l, (size_t)HDIM * SHI);

    router_kernel<<<NTOK / 8, 256>>>(x, gate_w);
    scan_kernel<<<1, 256>>>();

    // routed gate/up + SwiGLU -> g_ar (bf16 hi/lo)
    glu_bf16_kernel<<<dim3(IDIM / 64, CAP / 128, NEXP), 256, 3 * 32768>>>(
        x_h, x_l, HDIM, etok,
        wg_h, wg_l, wu_h, wu_l, (size_t)IDIM * HDIM,
        ar_h, ar_l, (size_t)CAP * IDIM, IDIM, HDIM, counts);

    // shared gate/up + SwiGLU -> g_as
    glu_bf16_kernel<<<dim3(SHI / 64, NTOK / 128, 1), 256, 3 * 32768>>>(
        x_h, x_l, HDIM, nullptr,
        sg_h, sg_l, su_h, su_l, 0,
        as_h, as_l, 0, SHI, HDIM, nullptr);

    // shared down-proj: initializes out
    down_bf16_kernel<<<dim3(HDIM / 64, NTOK / 128, 1), 256, 3 * 24576>>>(
        as_h, as_l, SHI, 0,
        sd_h, sd_l, 0,
        nullptr, nullptr, nullptr, NTOK,
        out, HDIM, SHI, /*accumulate=*/0);

    // routed down-proj: weighted scatter add
    down_bf16_kernel<<<dim3(HDIM / 64, CAP / 128, NEXP), 256, 3 * 24576>>>(
        ar_h, ar_l, IDIM, (size_t)CAP * IDIM,
        wd_h, wd_l, (size_t)HDIM * IDIM,
        etok, ewt, counts, 0,
        out, HDIM, IDIM, /*accumulate=*/1);
}